// round 13
// baseline (speedup 1.0000x reference)
#include <cuda_runtime.h>
#include <stdint.h>

// VDEmbedding: out[t,:] = (x[t]==0 ? 0 : mask[x[t]]) * weight[x[t], :]
// x: int32 [65536], weight: f32 [128000,128], mask: f32 [128000] -> out: f32 [65536,128]
//
// R12: single-variable experiment vs R11 (identical shape, 10.72us): gather
// uses ld.global.nc.L2::evict_last.v8.b32 to keep the 65.5MB weight table
// resident in L2 across graph replays; stores stay DEFAULT (R5's .cs and R6's
// store-side policy were confounds). Discriminates "LTS byte cap" (neutral)
// vs "warm-replay DRAM re-reads" (big win) as the 10.7us wall.

static constexpr int EMBED_DIM = 128;
static constexpr int PAD_IDX   = 0;
static constexpr int WARPS     = 8;   // 256 threads
static constexpr int TOK       = 2;   // tokens per warp (16 lanes each)

__global__ __launch_bounds__(256, 8)
void vdemb_kernel(const int* __restrict__ x,
                  const float* __restrict__ weight,
                  const float* __restrict__ mask,
                  float* __restrict__ out,
                  int n_tokens)
{
    int warp = threadIdx.x >> 5;
    int lane = threadIdx.x & 31;
    int half = lane >> 4;          // which of the warp's 2 tokens
    int sub  = lane & 15;          // 16-lane team position: 32B each
    int token = (blockIdx.x * WARPS + warp) * TOK + half;
    if (token >= n_tokens) return;

    int idx = __ldg(&x[token]);
    float s = (idx == PAD_IDX) ? 0.0f : __ldg(&mask[idx]);

    // one 256-bit gather, L2 evict_last: keep weight lines resident in L2
    const float* src = weight + (size_t)idx * EMBED_DIM + sub * 8;
    uint32_t r0, r1, r2, r3, r4, r5, r6, r7;
    asm volatile(
        "ld.global.nc.L2::evict_last.v8.b32 {%0,%1,%2,%3,%4,%5,%6,%7}, [%8];"
        : "=r"(r0), "=r"(r1), "=r"(r2), "=r"(r3),
          "=r"(r4), "=r"(r5), "=r"(r6), "=r"(r7)
        : "l"(src));

    float f0 = __uint_as_float(r0) * s;
    float f1 = __uint_as_float(r1) * s;
    float f2 = __uint_as_float(r2) * s;
    float f3 = __uint_as_float(r3) * s;
    float f4 = __uint_as_float(r4) * s;
    float f5 = __uint_as_float(r5) * s;
    float f6 = __uint_as_float(r6) * s;
    float f7 = __uint_as_float(r7) * s;

    // one 256-bit store, DEFAULT policy (proven best for stores)
    float* dst = out + (size_t)token * EMBED_DIM + sub * 8;
    asm volatile(
        "st.global.v8.b32 [%0], {%1,%2,%3,%4,%5,%6,%7,%8};"
        :: "l"(dst),
           "r"(__float_as_uint(f0)), "r"(__float_as_uint(f1)),
           "r"(__float_as_uint(f2)), "r"(__float_as_uint(f3)),
           "r"(__float_as_uint(f4)), "r"(__float_as_uint(f5)),
           "r"(__float_as_uint(f6)), "r"(__float_as_uint(f7)));
}

extern "C" void kernel_launch(void* const* d_in, const int* in_sizes, int n_in,
                              void* d_out, int out_size)
{
    const int*   x      = (const int*)d_in[0];
    const float* weight = (const float*)d_in[1];
    const float* mask   = (const float*)d_in[2];
    float*       out    = (float*)d_out;

    int n_tokens = in_sizes[0];                 // 65536
    int tokens_per_block = WARPS * TOK;         // 16
    int blocks = (n_tokens + tokens_per_block - 1) / tokens_per_block;  // 4096

    vdemb_kernel<<<blocks, 256>>>(x, weight, mask, out, n_tokens);
}